// round 15
// baseline (speedup 1.0000x reference)
#include <cuda_runtime.h>
#include <math.h>

#define Bc 8
#define Nc 4096
#define Dc 768
#define Ec 8
#define ESc 16
#define Hc 3072
#define NCH1 64
#define TOK1 64
#define TOK7 64

typedef unsigned long long u64;
typedef unsigned int u32;

// ----------------- scratch -----------------
__device__ float g_logits[Bc * Nc * ESc];
__device__ float g_pxs[Bc * NCH1 * ESc * Dc];
__device__ __align__(16) u64 g_xs2[Ec * Dc * 8];       // [e][d][rp]
__device__ float g_mch[Bc * NCH1 * ESc];
__device__ float g_sch[Bc * NCH1 * ESc];
__device__ float g_cmaxf[Bc * ESc];
__device__ float g_inv[Bc * ESc];
__device__ __align__(16) u64 g_h2[Ec * Hc * 8];        // [e][f][rp]
__device__ float g_ys[Bc * ESc * Dc];

// ----------------- f32x2 helpers -----------------
__device__ __forceinline__ u64 pk2(float x, float y) {
    u64 r; asm("mov.b64 %0, {%1, %2};" : "=l"(r) : "f"(x), "f"(y)); return r;
}
__device__ __forceinline__ u64 dup2(float x) {
    u64 r; asm("mov.b64 %0, {%1, %1};" : "=l"(r) : "f"(x)); return r;
}
__device__ __forceinline__ void up2(u64 v, float& x, float& y) {
    asm("mov.b64 {%0, %1}, %2;" : "=f"(x), "=f"(y) : "l"(v));
}
__device__ __forceinline__ void fma2(u64& d, u64 a, u64 b) {
    asm("fma.rn.f32x2 %0, %1, %2, %0;" : "+l"(d) : "l"(a), "l"(b));
}
__device__ __forceinline__ u64 add2(u64 a, u64 b) {
    u64 r; asm("add.rn.f32x2 %0, %1, %2;" : "=l"(r) : "l"(a), "l"(b)); return r;
}
__device__ __forceinline__ float gelu_exact(float v) {
    return 0.5f * v * (1.0f + erff(v * 0.70710678118654752f));
}

// ================= dummy (steer ncu 4th-launch capture onto k1) =========
__global__ void kd_noop() {}

// ---- k1 smem float offsets (double-buffered xT; red aliased onto xT0/xT1) ----
#define OFF_PHI  0                      // 12288 floats (u64[768*8])
#define OFF_XT0  12288                  // 64 x 65 = 4160 floats
#define OFF_XT1  16448                  // 64 x 65 = 4160 floats
#define OFF_RED  12288                  // aliased: 2048 u64 = 4096 floats (post-mainloop)
#define OFF_LSM  20608                  // 64 x 16
#define OFF_DSM  21632                  // 64 x 16
#define OFF_GM   22656                  // 16 x 16
#define OFF_PS   22912                  // 16 x 16
#define OFF_CM   23168                  // 16
#define K1_SMEM_FLOATS 23184            // 92736 B -> 2 blocks/SM

// ================= K1: fused logits + dispatch softmax + chunk colstats + partial xs ===
// grid (64, 8), 256 thr
extern "C" __global__ void __launch_bounds__(256)
k1_fused(const float* __restrict__ x, const float* __restrict__ phi) {
    extern __shared__ float smemf[];
    u64*   phiD = (u64*)(smemf + OFF_PHI);
    float* xT0  = smemf + OFF_XT0;
    float* xT1  = smemf + OFF_XT1;
    u64*   red  = (u64*)(smemf + OFF_RED);   // aliases xT0/xT1 — post-mainloop only
    float* lsm  = smemf + OFF_LSM;
    float* dsm  = smemf + OFF_DSM;
    float* gm   = smemf + OFF_GM;
    float* ps   = smemf + OFF_PS;
    float* cm   = smemf + OFF_CM;

    const int b = blockIdx.y, chunk = blockIdx.x;
    const int tid = threadIdx.x;
    const int lane = tid & 31, wid = tid >> 5;
    const float* xc = x + ((size_t)b * Nc + chunk * TOK1) * Dc;

    // staging thread coords (fixed across rounds)
    const int st_t = tid >> 2;                 // reused: idx = tid + k*256 decomposition
    (void)st_t;

    {   // phi [768][16] -> u64 pairs, straight copy
        const u64* ph = (const u64*)phi;
        for (int i = tid; i < Dc * 8; i += 256) phiD[i] = ph[i];
    }

    // ---- Phase A: pipelined. warp = K-segment; lane owns 2 tokens; 16 accs ----
    u64 acc[16];
    #pragma unroll
    for (int j = 0; j < 16; ++j) acc[j] = 0ull;

    float4 st[4];
    // prologue: stage d-block 0
    #pragma unroll
    for (int k = 0; k < 4; ++k) {
        const int idx = tid + k * 256;
        const int t = idx >> 4, dd4 = idx & 15;
        st[k] = __ldg((const float4*)(xc + (size_t)t * Dc + dd4 * 4));
    }
    #pragma unroll
    for (int k = 0; k < 4; ++k) {
        const int idx = tid + k * 256;
        const int t = idx >> 4, dd4 = idx & 15;
        xT0[(dd4 * 4 + 0) * 65 + t] = st[k].x;
        xT0[(dd4 * 4 + 1) * 65 + t] = st[k].y;
        xT0[(dd4 * 4 + 2) * 65 + t] = st[k].z;
        xT0[(dd4 * 4 + 3) * 65 + t] = st[k].w;
    }
    __syncthreads();

    for (int db = 0; db < 12; ++db) {
        float* cur = (db & 1) ? xT1 : xT0;
        float* nxt = (db & 1) ? xT0 : xT1;
        // issue loads for next block (latency hidden under compute)
        if (db < 11) {
            const int d0n = (db + 1) * 64;
            #pragma unroll
            for (int k = 0; k < 4; ++k) {
                const int idx = tid + k * 256;
                const int t = idx >> 4, dd4 = idx & 15;
                st[k] = __ldg((const float4*)(xc + (size_t)t * Dc + d0n + dd4 * 4));
            }
        }
        // compute on current buffer
        const int d0 = db * 64;
        const ulonglong2* pp = (const ulonglong2*)phiD;
        #pragma unroll
        for (int i = 0; i < 8; ++i) {
            const int dd = wid * 8 + i;
            const int d = d0 + dd;
            const u64 xa = dup2(cur[dd * 65 + lane]);
            const u64 xb = dup2(cur[dd * 65 + 32 + lane]);
            ulonglong2 q0 = pp[d * 4 + 0];
            ulonglong2 q1 = pp[d * 4 + 1];
            ulonglong2 q2 = pp[d * 4 + 2];
            ulonglong2 q3 = pp[d * 4 + 3];
            fma2(acc[0], xa, q0.x); fma2(acc[1], xa, q0.y);
            fma2(acc[2], xa, q1.x); fma2(acc[3], xa, q1.y);
            fma2(acc[4], xa, q2.x); fma2(acc[5], xa, q2.y);
            fma2(acc[6], xa, q3.x); fma2(acc[7], xa, q3.y);
            fma2(acc[8],  xb, q0.x); fma2(acc[9],  xb, q0.y);
            fma2(acc[10], xb, q1.x); fma2(acc[11], xb, q1.y);
            fma2(acc[12], xb, q2.x); fma2(acc[13], xb, q2.y);
            fma2(acc[14], xb, q3.x); fma2(acc[15], xb, q3.y);
        }
        // store staged regs into the other buffer
        if (db < 11) {
            #pragma unroll
            for (int k = 0; k < 4; ++k) {
                const int idx = tid + k * 256;
                const int t = idx >> 4, dd4 = idx & 15;
                nxt[(dd4 * 4 + 0) * 65 + t] = st[k].x;
                nxt[(dd4 * 4 + 1) * 65 + t] = st[k].y;
                nxt[(dd4 * 4 + 2) * 65 + t] = st[k].z;
                nxt[(dd4 * 4 + 3) * 65 + t] = st[k].w;
            }
        }
        __syncthreads();
    }
    // xT0/xT1 dead; red (aliased) becomes live

    // ---- 3-stage tree reduce over 8 warps ----
    if (wid >= 4) {
        u64* r = red + ((wid - 4) * 32 + lane) * 16;
        #pragma unroll
        for (int j = 0; j < 16; ++j) r[j] = acc[j];
    }
    __syncthreads();
    if (wid < 4) {
        const u64* r = red + (wid * 32 + lane) * 16;
        #pragma unroll
        for (int j = 0; j < 16; ++j) acc[j] = add2(acc[j], r[j]);
    }
    __syncthreads();
    if (wid >= 2 && wid < 4) {
        u64* r = red + ((wid - 2) * 32 + lane) * 16;
        #pragma unroll
        for (int j = 0; j < 16; ++j) r[j] = acc[j];
    }
    __syncthreads();
    if (wid < 2) {
        const u64* r = red + (wid * 32 + lane) * 16;
        #pragma unroll
        for (int j = 0; j < 16; ++j) acc[j] = add2(acc[j], r[j]);
    }
    __syncthreads();
    if (wid == 1) {
        u64* r = red + lane * 16;
        #pragma unroll
        for (int j = 0; j < 16; ++j) r[j] = acc[j];
    }
    __syncthreads();
    if (wid == 0) {
        const u64* r = red + lane * 16;
        #pragma unroll
        for (int j = 0; j < 16; ++j) acc[j] = add2(acc[j], r[j]);
        u64* dl = (u64*)dsm;
        u64* ll = (u64*)lsm;
        #pragma unroll
        for (int h = 0; h < 2; ++h) {
            float l[16];
            #pragma unroll
            for (int j = 0; j < 8; ++j) up2(acc[h * 8 + j], l[2 * j], l[2 * j + 1]);
            float m = l[0];
            #pragma unroll
            for (int es = 1; es < 16; ++es) m = fmaxf(m, l[es]);
            float s = 0.f;
            float p[16];
            #pragma unroll
            for (int es = 0; es < 16; ++es) { p[es] = __expf(l[es] - m); s += p[es]; }
            const float inv = 1.f / s;
            const int tk = lane + h * 32;
            #pragma unroll
            for (int j = 0; j < 8; ++j) {
                dl[tk * 8 + j] = pk2(p[2 * j] * inv, p[2 * j + 1] * inv);
                ll[tk * 8 + j] = pk2(l[2 * j], l[2 * j + 1]);
            }
        }
    }
    __syncthreads();

    {   // raw logits -> global
        const size_t lbase = ((size_t)b * Nc + chunk * TOK1) * ESc;
        #pragma unroll
        for (int k = 0; k < 4; ++k) g_logits[lbase + tid + k * 256] = lsm[tid + k * 256];
    }

    // ---- Phase B: per-chunk column stats (16 groups x 4 tokens) ----
    {
        const int g = tid >> 4, es = tid & 15;
        float m = -1e30f;
        #pragma unroll
        for (int t4 = 0; t4 < 4; ++t4) m = fmaxf(m, lsm[(g * 4 + t4) * ESc + es]);
        gm[g * 16 + es] = m;
    }
    __syncthreads();
    if (tid < 16) {
        float m = gm[tid];
        #pragma unroll
        for (int g = 1; g < 16; ++g) m = fmaxf(m, gm[g * 16 + tid]);
        cm[tid] = m;
    }
    __syncthreads();
    {
        const int g = tid >> 4, es = tid & 15;
        const float m = cm[es];
        float p = 0.f;
        #pragma unroll
        for (int t4 = 0; t4 < 4; ++t4) p += __expf(lsm[(g * 4 + t4) * ESc + es] - m);
        ps[g * 16 + es] = p;
    }
    __syncthreads();
    if (tid < 16) {
        float s = 0.f;
        #pragma unroll
        for (int g = 0; g < 16; ++g) s += ps[g * 16 + tid];
        g_mch[((size_t)b * NCH1 + chunk) * ESc + tid] = cm[tid];
        g_sch[((size_t)b * NCH1 + chunk) * ESc + tid] = s;
    }

    // ---- Phase C: partial xs, thread = (12 d as 3 float4) x (4 es), unroll 4 ----
    {
        const int f4i = tid & 63;
        const int esq = tid >> 6;
        u64 acc2[4][3][2];
        #pragma unroll
        for (int e = 0; e < 4; ++e)
            #pragma unroll
            for (int j = 0; j < 3; ++j) { acc2[e][j][0] = 0ull; acc2[e][j][1] = 0ull; }

        const int dbase = f4i * 4;
        #pragma unroll 4
        for (int t = 0; t < TOK1; ++t) {
            const float4 xv0 = __ldg((const float4*)(xc + (size_t)t * Dc + dbase));
            const float4 xv1 = __ldg((const float4*)(xc + (size_t)t * Dc + dbase + 256));
            const float4 xv2 = __ldg((const float4*)(xc + (size_t)t * Dc + dbase + 512));
            const u64 x0l = pk2(xv0.x, xv0.y), x0h = pk2(xv0.z, xv0.w);
            const u64 x1l = pk2(xv1.x, xv1.y), x1h = pk2(xv1.z, xv1.w);
            const u64 x2l = pk2(xv2.x, xv2.y), x2h = pk2(xv2.z, xv2.w);
            const float4 dv = *(const float4*)&dsm[t * ESc + esq * 4];
            const u64 w0 = dup2(dv.x), w1 = dup2(dv.y), w2 = dup2(dv.z), w3 = dup2(dv.w);
            fma2(acc2[0][0][0], w0, x0l); fma2(acc2[0][0][1], w0, x0h);
            fma2(acc2[0][1][0], w0, x1l); fma2(acc2[0][1][1], w0, x1h);
            fma2(acc2[0][2][0], w0, x2l); fma2(acc2[0][2][1], w0, x2h);
            fma2(acc2[1][0][0], w1, x0l); fma2(acc2[1][0][1], w1, x0h);
            fma2(acc2[1][1][0], w1, x1l); fma2(acc2[1][1][1], w1, x1h);
            fma2(acc2[1][2][0], w1, x2l); fma2(acc2[1][2][1], w1, x2h);
            fma2(acc2[2][0][0], w2, x0l); fma2(acc2[2][0][1], w2, x0h);
            fma2(acc2[2][1][0], w2, x1l); fma2(acc2[2][1][1], w2, x1h);
            fma2(acc2[2][2][0], w2, x2l); fma2(acc2[2][2][1], w2, x2h);
            fma2(acc2[3][0][0], w3, x0l); fma2(acc2[3][0][1], w3, x0h);
            fma2(acc2[3][1][0], w3, x1l); fma2(acc2[3][1][1], w3, x1h);
            fma2(acc2[3][2][0], w3, x2l); fma2(acc2[3][2][1], w3, x2h);
        }
        float* out = g_pxs + ((size_t)(b * NCH1 + chunk) * ESc) * Dc;
        #pragma unroll
        for (int e = 0; e < 4; ++e) {
            const int es = esq * 4 + e;
            #pragma unroll
            for (int j = 0; j < 3; ++j) {
                float4 o;
                up2(acc2[e][j][0], o.x, o.y);
                up2(acc2[e][j][1], o.z, o.w);
                *(float4*)(out + (size_t)es * Dc + dbase + 256 * j) = o;
            }
        }
    }
}

// ================= K2: vectorized reduce of xs partials + colstat finalize =========
__global__ void __launch_bounds__(256) k2_reduce_xs() {
    const int idx = blockIdx.x * 256 + threadIdx.x;    // 0..24575 float4 units
    const int b = idx / (ESc * Dc / 4);
    const int rem4 = idx % (ESc * Dc / 4);
    const int es = rem4 / (Dc / 4), d4 = rem4 % (Dc / 4);
    float4 s = make_float4(0.f, 0.f, 0.f, 0.f);
    const float4* base = (const float4*)(g_pxs) + (size_t)b * NCH1 * (ESc * Dc / 4) + rem4;
    #pragma unroll 8
    for (int c = 0; c < NCH1; ++c) {
        const float4 v = __ldg(base + (size_t)c * (ESc * Dc / 4));
        s.x += v.x; s.y += v.y; s.z += v.z; s.w += v.w;
    }
    const int e = es >> 1, sl = es & 1, row = b * 2 + sl;
    float* xs = (float*)g_xs2;
    const int d = d4 * 4;
    xs[((size_t)e * Dc + d + 0) * 16 + row] = s.x;
    xs[((size_t)e * Dc + d + 1) * 16 + row] = s.y;
    xs[((size_t)e * Dc + d + 2) * 16 + row] = s.z;
    xs[((size_t)e * Dc + d + 3) * 16 + row] = s.w;

    if (blockIdx.x == 0 && threadIdx.x < Bc * ESc) {
        const int i = threadIdx.x;
        const int bb = i >> 4, ees = i & 15;
        float M = -1e30f;
        #pragma unroll 8
        for (int c = 0; c < NCH1; ++c)
            M = fmaxf(M, g_mch[((size_t)bb * NCH1 + c) * ESc + ees]);
        float S = 0.f;
        #pragma unroll 8
        for (int c = 0; c < NCH1; ++c) {
            const size_t o = ((size_t)bb * NCH1 + c) * ESc + ees;
            S += __expf(g_mch[o] - M) * g_sch[o];
        }
        g_cmaxf[i] = M;
        g_inv[i] = 1.f / S;
    }
}

// ================= K5: FFN1 + GELU  (grid (48, 8), 256 thr) =================
#define K5_SMEM_BYTES (Dc * 8 * 8 + 2048 * 8)   // 65536
__global__ void __launch_bounds__(256, 3)
k5_ffn1(const float* __restrict__ w1, const float* __restrict__ b1) {
    extern __shared__ __align__(16) char k5smem[];
    u64* xsm = (u64*)k5smem;
    u64* red = xsm + Dc * 8;
    const int e = blockIdx.y;
    const int fbase = blockIdx.x * 64;
    const int tid = threadIdx.x;
    {
        const ulonglong2* src = (const ulonglong2*)(g_xs2 + (size_t)e * Dc * 8);
        ulonglong2* dst = (ulonglong2*)xsm;
        #pragma unroll
        for (int k = 0; k < 12; ++k) dst[tid + k * 256] = src[tid + k * 256];
    }
    __syncthreads();

    const int fi = tid & 15;
    const int rh = (tid >> 4) & 1;
    const int ds = tid >> 5;
    const int lid32 = tid & 31;
    const int f = fbase + fi * 4;

    u64 acc[4][4];
    #pragma unroll
    for (int j = 0; j < 4; ++j)
        #pragma unroll
        for (int r = 0; r < 4; ++r) acc[j][r] = 0ull;

    const float* w = w1 + (size_t)e * Dc * Hc + f;
    const ulonglong2* x2 = (const ulonglong2*)xsm;
    const int dlo = ds * 96;
    #pragma unroll 8
    for (int d = dlo; d < dlo + 96; ++d) {
        const float4 wv = __ldg((const float4*)(w + (size_t)d * Hc));
        const ulonglong2 xa = x2[d * 4 + rh * 2];
        const ulonglong2 xb = x2[d * 4 + rh * 2 + 1];
        const u64 w0 = dup2(wv.x), w1d = dup2(wv.y), w2 = dup2(wv.z), w3 = dup2(wv.w);
        fma2(acc[0][0], w0, xa.x); fma2(acc[0][1], w0, xa.y);
        fma2(acc[0][2], w0, xb.x); fma2(acc[0][3], w0, xb.y);
        fma2(acc[1][0], w1d, xa.x); fma2(acc[1][1], w1d, xa.y);
        fma2(acc[1][2], w1d, xb.x); fma2(acc[1][3], w1d, xb.y);
        fma2(acc[2][0], w2, xa.x); fma2(acc[2][1], w2, xa.y);
        fma2(acc[2][2], w2, xb.x); fma2(acc[2][3], w2, xb.y);
        fma2(acc[3][0], w3, xa.x); fma2(acc[3][1], w3, xa.y);
        fma2(acc[3][2], w3, xb.x); fma2(acc[3][3], w3, xb.y);
    }

    if (ds >= 4) {
        u64* r = red + ((ds - 4) * 32 + lid32) * 16;
        #pragma unroll
        for (int j = 0; j < 4; ++j)
            #pragma unroll
            for (int k = 0; k < 4; ++k) r[j * 4 + k] = acc[j][k];
    }
    __syncthreads();
    if (ds < 4) {
        const u64* r = red + (ds * 32 + lid32) * 16;
        #pragma unroll
        for (int j = 0; j < 4; ++j)
            #pragma unroll
            for (int k = 0; k < 4; ++k) acc[j][k] = add2(acc[j][k], r[j * 4 + k]);
    }
    __syncthreads();
    if (ds >= 2 && ds < 4) {
        u64* r = red + ((ds - 2) * 32 + lid32) * 16;
        #pragma unroll
        for (int j = 0; j < 4; ++j)
            #pragma unroll
            for (int k = 0; k < 4; ++k) r[j * 4 + k] = acc[j][k];
    }
    __syncthreads();
    if (ds < 2) {
        const u64* r = red + (ds * 32 + lid32) * 16;
        #pragma unroll
        for (int j = 0; j < 4; ++j)
            #pragma unroll
            for (int k = 0; k < 4; ++k) acc[j][k] = add2(acc[j][k], r[j * 4 + k]);
    }
    __syncthreads();
    if (ds == 1) {
        u64* r = red + lid32 * 16;
        #pragma unroll
        for (int j = 0; j < 4; ++j)
            #pragma unroll
            for (int k = 0; k < 4; ++k) r[j * 4 + k] = acc[j][k];
    }
    __syncthreads();
    if (ds == 0) {
        u64* r = red + lid32 * 16;
        #pragma unroll
        for (int j = 0; j < 4; ++j)
            #pragma unroll
            for (int k = 0; k < 4; ++k) r[j * 4 + k] = add2(acc[j][k], r[j * 4 + k]);
    }
    __syncthreads();
    #pragma unroll
    for (int q = 0; q < 2; ++q) {
        const int flat = tid * 2 + q;
        const int t32 = flat >> 4, j = flat & 15;
        const int fi2 = t32 & 15, rh2 = t32 >> 4;
        const int jf = j >> 2, jr = j & 3;
        const int f2 = fbase + fi2 * 4 + jf;
        const int rp = rh2 * 4 + jr;
        const float bv = __ldg(b1 + (size_t)e * Hc + f2);
        float lo, hi; up2(red[flat], lo, hi);
        g_h2[((size_t)e * Hc + f2) * 8 + rp] =
            pk2(gelu_exact(lo + bv), gelu_exact(hi + bv));
    }
}

// ================= K6: FFN2 + bias  (grid (48, 8), 256 thr) =================
__global__ void __launch_bounds__(256, 3)
k6_ffn2(const float* __restrict__ w2, const float* __restrict__ b2) {
    __shared__ __align__(16) u64 red[32 * 128];
    const int e = blockIdx.y;
    const int d0 = blockIdx.x * 16;
    const int tid = threadIdx.x;
    const int dq = tid & 3, rh = (tid >> 2) & 1, fs = tid >> 3;

    u64 acc[4][4];
    #pragma unroll
    for (int j = 0; j < 4; ++j)
        #pragma unroll
        for (int r = 0; r < 4; ++r) acc[j][r] = 0ull;

    const float* w = w2 + (size_t)e * Hc * Dc + d0 + dq * 4;
    const ulonglong2* h2 = (const ulonglong2*)(g_h2 + (size_t)e * Hc * 8);
    const int f0 = fs * 96;
    #pragma unroll 8
    for (int f = f0; f < f0 + 96; ++f) {
        const float4 wv = __ldg((const float4*)(w + (size_t)f * Dc));
        const ulonglong2 ha = h2[f * 4 + rh * 2];
        const ulonglong2 hb = h2[f * 4 + rh * 2 + 1];
        const u64 wd0 = dup2(wv.x), wd1 = dup2(wv.y), wd2 = dup2(wv.z), wd3 = dup2(wv.w);
        fma2(acc[0][0], wd0, ha.x); fma2(acc[0][1], wd0, ha.y);
        fma2(acc[0][2], wd0, hb.x); fma2(acc[0][3], wd0, hb.y);
        fma2(acc[1][0], wd1, ha.x); fma2(acc[1][1], wd1, ha.y);
        fma2(acc[1][2], wd1, hb.x); fma2(acc[1][3], wd1, hb.y);
        fma2(acc[2][0], wd2, ha.x); fma2(acc[2][1], wd2, ha.y);
        fma2(acc[2][2], wd2, hb.x); fma2(acc[2][3], wd2, hb.y);
        fma2(acc[3][0], wd3, ha.x); fma2(acc[3][1], wd3, ha.y);
        fma2(acc[3][2], wd3, hb.x); fma2(acc[3][3], wd3, hb.y);
    }
    #pragma unroll
    for (int j = 0; j < 4; ++j)
        #pragma unroll
        for (int r = 0; r < 4; ++r)
            red[fs * 128 + (dq * 4 + j) * 8 + rh * 4 + r] = acc[j][r];
    __syncthreads();
    if (tid < 128) {
        const int d_loc = tid >> 3, rp = tid & 7;
        u64 s = red[d_loc * 8 + rp];
        #pragma unroll 8
        for (int f2 = 1; f2 < 32; ++f2) s = add2(s, red[f2 * 128 + d_loc * 8 + rp]);
        float lo, hi; up2(s, lo, hi);
        const float bb2 = __ldg(b2 + (size_t)e * Dc + d0 + d_loc);
        const int r0 = 2 * rp, r1 = 2 * rp + 1;
        g_ys[((size_t)(r0 >> 1) * ESc + e * 2 + (r0 & 1)) * Dc + d0 + d_loc] = lo + bb2;
        g_ys[((size_t)(r1 >> 1) * ESc + e * 2 + (r1 & 1)) * Dc + d0 + d_loc] = hi + bb2;
    }
}

// ================= K7: combine softmax + y = c @ ys  (grid (64, 8)) =================
#define K7_SMEM_FLOATS (ESc * Dc + ESc * TOK7 + 32)
extern "C" __global__ void __launch_bounds__(256)
k7_combine(float* __restrict__ y) {
    extern __shared__ float smemf[];
    float* ysm = smemf;
    float* csm = smemf + ESc * Dc;
    float* cm  = smemf + ESc * Dc + ESc * TOK7;
    float* inv = cm + 16;

    const int b = blockIdx.y, chunk = blockIdx.x, tid = threadIdx.x;
    {
        const float4* src = (const float4*)(g_ys + (size_t)b * ESc * Dc);
        float4* dst = (float4*)ysm;
        #pragma unroll
        for (int k = 0; k < 12; ++k) dst[tid + k * 256] = src[tid + k * 256];
    }
    if (tid < 16) { cm[tid] = g_cmaxf[b * ESc + tid]; inv[tid] = g_inv[b * ESc + tid]; }
    __syncthreads();

    {
        const int i0 = tid * 4;
        const int es = i0 >> 6;
        const int t0 = i0 & 63;
        const float m = cm[es], iv = inv[es];
        const float* lp = g_logits + ((size_t)b * Nc + chunk * TOK7 + t0) * ESc + es;
        #pragma unroll
        for (int q = 0; q < 4; ++q)
            csm[es * TOK7 + t0 + q] = __expf(lp[q * ESc] - m) * iv;
    }
    __syncthreads();

    const int dg = tid & 63, tg = tid >> 6;
    const int dbase = dg * 4;
    float* yb = y + ((size_t)b * Nc + chunk * TOK7) * Dc;
    for (int tq = 0; tq < 4; ++tq) {
        const int trel = tg * 16 + tq * 4;
        u64 acc[4][3][2];
        #pragma unroll
        for (int t = 0; t < 4; ++t)
            #pragma unroll
            for (int j = 0; j < 3; ++j) { acc[t][j][0] = 0ull; acc[t][j][1] = 0ull; }
        #pragma unroll
        for (int es = 0; es < 16; ++es) {
            float4 c4 = *(const float4*)&csm[es * TOK7 + trel];
            u64 cd0 = dup2(c4.x), cd1 = dup2(c4.y), cd2 = dup2(c4.z), cd3 = dup2(c4.w);
            #pragma unroll
            for (int j = 0; j < 3; ++j) {
                float4 yv = *(const float4*)&ysm[es * Dc + dbase + 256 * j];
                u64 ylo = pk2(yv.x, yv.y), yhi = pk2(yv.z, yv.w);
                fma2(acc[0][j][0], cd0, ylo); fma2(acc[0][j][1], cd0, yhi);
                fma2(acc[1][j][0], cd1, ylo); fma2(acc[1][j][1], cd1, yhi);
                fma2(acc[2][j][0], cd2, ylo); fma2(acc[2][j][1], cd2, yhi);
                fma2(acc[3][j][0], cd3, ylo); fma2(acc[3][j][1], cd3, yhi);
            }
        }
        #pragma unroll
        for (int t = 0; t < 4; ++t) {
            float* yr = yb + (size_t)(trel + t) * Dc;
            #pragma unroll
            for (int j = 0; j < 3; ++j) {
                float4 o;
                up2(acc[t][j][0], o.x, o.y);
                up2(acc[t][j][1], o.z, o.w);
                *(float4*)(yr + dbase + 256 * j) = o;
            }
        }
    }
}

// ================= host =================
extern "C" void kernel_launch(void* const* d_in, const int* in_sizes, int n_in,
                              void* d_out, int out_size) {
    const float* x   = (const float*)d_in[0];
    const float* phi = (const float*)d_in[1];
    const float* w1  = (const float*)d_in[2];
    const float* b1  = (const float*)d_in[3];
    const float* w2  = (const float*)d_in[4];
    const float* b2  = (const float*)d_in[5];
    float* y = (float*)d_out;

    cudaFuncSetAttribute(k1_fused, cudaFuncAttributeMaxDynamicSharedMemorySize,
                         K1_SMEM_FLOATS * sizeof(float));
    cudaFuncSetAttribute(k5_ffn1, cudaFuncAttributeMaxDynamicSharedMemorySize,
                         K5_SMEM_BYTES);
    cudaFuncSetAttribute(k7_combine, cudaFuncAttributeMaxDynamicSharedMemorySize,
                         K7_SMEM_FLOATS * sizeof(float));
    (void)in_sizes; (void)n_in; (void)out_size;

    // 3 no-ops: 4th launch (profiled) = k1_fused
    kd_noop<<<1, 32>>>();
    kd_noop<<<1, 32>>>();
    kd_noop<<<1, 32>>>();
    k1_fused<<<dim3(NCH1, Bc), 256, K1_SMEM_FLOATS * sizeof(float)>>>(x, phi);
    k2_reduce_xs<<<96, 256>>>();
    k5_ffn1<<<dim3(Hc / 64, Ec), 256, K5_SMEM_BYTES>>>(w1, b1);
    k6_ffn2<<<dim3(Dc / 16, Ec), 256>>>(w2, b2);
    k7_combine<<<dim3(Nc / TOK7, Bc), 256, K7_SMEM_FLOATS * sizeof(float)>>>(y);
}

// round 16
// speedup vs baseline: 1.0318x; 1.0318x over previous
#include <cuda_runtime.h>
#include <math.h>

#define Bc 8
#define Nc 4096
#define Dc 768
#define Ec 8
#define ESc 16
#define Hc 3072
#define NCH1 64
#define TOK1 64
#define TOK7 64

typedef unsigned long long u64;
typedef unsigned int u32;

// ----------------- scratch -----------------
__device__ float g_logits[Bc * Nc * ESc];
__device__ float g_pxs[Bc * NCH1 * ESc * Dc];
__device__ __align__(16) u64 g_xs2[Ec * Dc * 8];       // [e][d][rp]
__device__ float g_mch[Bc * NCH1 * ESc];
__device__ float g_sch[Bc * NCH1 * ESc];
__device__ float g_cmaxf[Bc * ESc];
__device__ float g_inv[Bc * ESc];
__device__ __align__(16) u64 g_h2[Ec * Hc * 8];        // [e][f][rp]
__device__ float g_ys[Bc * ESc * Dc];

// ----------------- f32x2 helpers -----------------
__device__ __forceinline__ u64 pk2(float x, float y) {
    u64 r; asm("mov.b64 %0, {%1, %2};" : "=l"(r) : "f"(x), "f"(y)); return r;
}
__device__ __forceinline__ u64 dup2(float x) {
    u64 r; asm("mov.b64 %0, {%1, %1};" : "=l"(r) : "f"(x)); return r;
}
__device__ __forceinline__ void up2(u64 v, float& x, float& y) {
    asm("mov.b64 {%0, %1}, %2;" : "=f"(x), "=f"(y) : "l"(v));
}
__device__ __forceinline__ void fma2(u64& d, u64 a, u64 b) {
    asm("fma.rn.f32x2 %0, %1, %2, %0;" : "+l"(d) : "l"(a), "l"(b));
}
__device__ __forceinline__ u64 add2(u64 a, u64 b) {
    u64 r; asm("add.rn.f32x2 %0, %1, %2;" : "=l"(r) : "l"(a), "l"(b)); return r;
}
__device__ __forceinline__ float gelu_exact(float v) {
    return 0.5f * v * (1.0f + erff(v * 0.70710678118654752f));
}

// ================= dummy (steer ncu 4th-launch capture onto k1) =========
__global__ void kd_noop() {}

// ---- k1 smem float offsets (red ALIASED onto xT) ----
#define OFF_PHI  0                      // 12288 floats (u64[768*8])
#define OFF_XT   12288                  // 64 x 65 = 4160 floats (mainloop only)
#define OFF_RED  12288                  // aliased: 2080 u64 capacity (post-mainloop)
#define OFF_LSM  16448                  // 64 x 16
#define OFF_DSM  17472                  // 64 x 16
#define OFF_GM   18496                  // 16 x 16
#define OFF_PS   18752                  // 16 x 16
#define OFF_CM   19008                  // 16
#define K1_SMEM_FLOATS 19024            // 76096 B

// ================= K1: fused logits + dispatch softmax + chunk colstats + partial xs ===
// grid (64, 8), 256 thr
extern "C" __global__ void __launch_bounds__(256)
k1_fused(const float* __restrict__ x, const float* __restrict__ phi) {
    extern __shared__ float smemf[];
    u64*   phiD = (u64*)(smemf + OFF_PHI);
    float* xT   = smemf + OFF_XT;
    u64*   red  = (u64*)(smemf + OFF_RED);   // aliases xT — only used after mainloop
    float* lsm  = smemf + OFF_LSM;
    float* dsm  = smemf + OFF_DSM;
    float* gm   = smemf + OFF_GM;
    float* ps   = smemf + OFF_PS;
    float* cm   = smemf + OFF_CM;

    const int b = blockIdx.y, chunk = blockIdx.x;
    const int tid = threadIdx.x;
    const int lane = tid & 31, wid = tid >> 5;
    const float* xc = x + ((size_t)b * Nc + chunk * TOK1) * Dc;

    {   // phi [768][16] -> u64 pairs, straight copy
        const u64* ph = (const u64*)phi;
        for (int i = tid; i < Dc * 8; i += 256) phiD[i] = ph[i];
    }

    // ---- Phase A: logits. warp = K-segment (8 d per 64-d block); lane owns 2 tokens ---
    u64 acc[16];               // [0..7]: token=lane, [8..15]: token=lane+32
    #pragma unroll
    for (int j = 0; j < 16; ++j) acc[j] = 0ull;

    for (int db = 0; db < 12; ++db) {
        const int d0 = db * 64;
        __syncthreads();
        // stage x[64 tok][64 d] transposed via float4 loads
        #pragma unroll
        for (int k = 0; k < 4; ++k) {
            const int idx = tid + k * 256;          // 0..1023
            const int t = idx >> 4, dd4 = idx & 15;
            const float4 v = __ldg((const float4*)(xc + (size_t)t * Dc + d0 + dd4 * 4));
            xT[(dd4 * 4 + 0) * 65 + t] = v.x;
            xT[(dd4 * 4 + 1) * 65 + t] = v.y;
            xT[(dd4 * 4 + 2) * 65 + t] = v.z;
            xT[(dd4 * 4 + 3) * 65 + t] = v.w;
        }
        __syncthreads();
        const ulonglong2* pp = (const ulonglong2*)phiD;
        #pragma unroll
        for (int i = 0; i < 8; ++i) {
            const int dd = wid * 8 + i;
            const int d = d0 + dd;
            const u64 xa = dup2(xT[dd * 65 + lane]);
            const u64 xb = dup2(xT[dd * 65 + 32 + lane]);
            ulonglong2 q0 = pp[d * 4 + 0];
            ulonglong2 q1 = pp[d * 4 + 1];
            ulonglong2 q2 = pp[d * 4 + 2];
            ulonglong2 q3 = pp[d * 4 + 3];
            fma2(acc[0], xa, q0.x); fma2(acc[1], xa, q0.y);
            fma2(acc[2], xa, q1.x); fma2(acc[3], xa, q1.y);
            fma2(acc[4], xa, q2.x); fma2(acc[5], xa, q2.y);
            fma2(acc[6], xa, q3.x); fma2(acc[7], xa, q3.y);
            fma2(acc[8],  xb, q0.x); fma2(acc[9],  xb, q0.y);
            fma2(acc[10], xb, q1.x); fma2(acc[11], xb, q1.y);
            fma2(acc[12], xb, q2.x); fma2(acc[13], xb, q2.y);
            fma2(acc[14], xb, q3.x); fma2(acc[15], xb, q3.y);
        }
    }
    __syncthreads();      // xT dead; red (aliased) becomes live

    // ---- 3-stage tree reduce over 8 warps ----
    if (wid >= 4) {
        u64* r = red + ((wid - 4) * 32 + lane) * 16;
        #pragma unroll
        for (int j = 0; j < 16; ++j) r[j] = acc[j];
    }
    __syncthreads();
    if (wid < 4) {
        const u64* r = red + (wid * 32 + lane) * 16;
        #pragma unroll
        for (int j = 0; j < 16; ++j) acc[j] = add2(acc[j], r[j]);
    }
    __syncthreads();
    if (wid >= 2 && wid < 4) {
        u64* r = red + ((wid - 2) * 32 + lane) * 16;
        #pragma unroll
        for (int j = 0; j < 16; ++j) r[j] = acc[j];
    }
    __syncthreads();
    if (wid < 2) {
        const u64* r = red + (wid * 32 + lane) * 16;
        #pragma unroll
        for (int j = 0; j < 16; ++j) acc[j] = add2(acc[j], r[j]);
    }
    __syncthreads();
    if (wid == 1) {
        u64* r = red + lane * 16;
        #pragma unroll
        for (int j = 0; j < 16; ++j) r[j] = acc[j];
    }
    __syncthreads();
    if (wid == 0) {
        const u64* r = red + lane * 16;
        #pragma unroll
        for (int j = 0; j < 16; ++j) acc[j] = add2(acc[j], r[j]);
        u64* dl = (u64*)dsm;
        u64* ll = (u64*)lsm;
        #pragma unroll
        for (int h = 0; h < 2; ++h) {
            float l[16];
            #pragma unroll
            for (int j = 0; j < 8; ++j) up2(acc[h * 8 + j], l[2 * j], l[2 * j + 1]);
            float m = l[0];
            #pragma unroll
            for (int es = 1; es < 16; ++es) m = fmaxf(m, l[es]);
            float s = 0.f;
            float p[16];
            #pragma unroll
            for (int es = 0; es < 16; ++es) { p[es] = __expf(l[es] - m); s += p[es]; }
            const float inv = 1.f / s;
            const int tk = lane + h * 32;
            #pragma unroll
            for (int j = 0; j < 8; ++j) {
                dl[tk * 8 + j] = pk2(p[2 * j] * inv, p[2 * j + 1] * inv);
                ll[tk * 8 + j] = pk2(l[2 * j], l[2 * j + 1]);
            }
        }
    }
    __syncthreads();

    {   // raw logits -> global
        const size_t lbase = ((size_t)b * Nc + chunk * TOK1) * ESc;
        #pragma unroll
        for (int k = 0; k < 4; ++k) g_logits[lbase + tid + k * 256] = lsm[tid + k * 256];
    }

    // ---- Phase B: per-chunk column stats (16 groups x 4 tokens) ----
    {
        const int g = tid >> 4, es = tid & 15;
        float m = -1e30f;
        #pragma unroll
        for (int t4 = 0; t4 < 4; ++t4) m = fmaxf(m, lsm[(g * 4 + t4) * ESc + es]);
        gm[g * 16 + es] = m;
    }
    __syncthreads();
    if (tid < 16) {
        float m = gm[tid];
        #pragma unroll
        for (int g = 1; g < 16; ++g) m = fmaxf(m, gm[g * 16 + tid]);
        cm[tid] = m;
    }
    __syncthreads();
    {
        const int g = tid >> 4, es = tid & 15;
        const float m = cm[es];
        float p = 0.f;
        #pragma unroll
        for (int t4 = 0; t4 < 4; ++t4) p += __expf(lsm[(g * 4 + t4) * ESc + es] - m);
        ps[g * 16 + es] = p;
    }
    __syncthreads();
    if (tid < 16) {
        float s = 0.f;
        #pragma unroll
        for (int g = 0; g < 16; ++g) s += ps[g * 16 + tid];
        g_mch[((size_t)b * NCH1 + chunk) * ESc + tid] = cm[tid];
        g_sch[((size_t)b * NCH1 + chunk) * ESc + tid] = s;
    }

    // ---- Phase C: partial xs, thread = (12 d as 3 float4) x (4 es), unroll 8 ----
    {
        const int f4i = tid & 63;
        const int esq = tid >> 6;
        u64 acc2[4][3][2];
        #pragma unroll
        for (int e = 0; e < 4; ++e)
            #pragma unroll
            for (int j = 0; j < 3; ++j) { acc2[e][j][0] = 0ull; acc2[e][j][1] = 0ull; }

        const int dbase = f4i * 4;
        #pragma unroll 8
        for (int t = 0; t < TOK1; ++t) {
            const float4 xv0 = __ldg((const float4*)(xc + (size_t)t * Dc + dbase));
            const float4 xv1 = __ldg((const float4*)(xc + (size_t)t * Dc + dbase + 256));
            const float4 xv2 = __ldg((const float4*)(xc + (size_t)t * Dc + dbase + 512));
            const u64 x0l = pk2(xv0.x, xv0.y), x0h = pk2(xv0.z, xv0.w);
            const u64 x1l = pk2(xv1.x, xv1.y), x1h = pk2(xv1.z, xv1.w);
            const u64 x2l = pk2(xv2.x, xv2.y), x2h = pk2(xv2.z, xv2.w);
            const float4 dv = *(const float4*)&dsm[t * ESc + esq * 4];
            const u64 w0 = dup2(dv.x), w1 = dup2(dv.y), w2 = dup2(dv.z), w3 = dup2(dv.w);
            fma2(acc2[0][0][0], w0, x0l); fma2(acc2[0][0][1], w0, x0h);
            fma2(acc2[0][1][0], w0, x1l); fma2(acc2[0][1][1], w0, x1h);
            fma2(acc2[0][2][0], w0, x2l); fma2(acc2[0][2][1], w0, x2h);
            fma2(acc2[1][0][0], w1, x0l); fma2(acc2[1][0][1], w1, x0h);
            fma2(acc2[1][1][0], w1, x1l); fma2(acc2[1][1][1], w1, x1h);
            fma2(acc2[1][2][0], w1, x2l); fma2(acc2[1][2][1], w1, x2h);
            fma2(acc2[2][0][0], w2, x0l); fma2(acc2[2][0][1], w2, x0h);
            fma2(acc2[2][1][0], w2, x1l); fma2(acc2[2][1][1], w2, x1h);
            fma2(acc2[2][2][0], w2, x2l); fma2(acc2[2][2][1], w2, x2h);
            fma2(acc2[3][0][0], w3, x0l); fma2(acc2[3][0][1], w3, x0h);
            fma2(acc2[3][1][0], w3, x1l); fma2(acc2[3][1][1], w3, x1h);
            fma2(acc2[3][2][0], w3, x2l); fma2(acc2[3][2][1], w3, x2h);
        }
        float* out = g_pxs + ((size_t)(b * NCH1 + chunk) * ESc) * Dc;
        #pragma unroll
        for (int e = 0; e < 4; ++e) {
            const int es = esq * 4 + e;
            #pragma unroll
            for (int j = 0; j < 3; ++j) {
                float4 o;
                up2(acc2[e][j][0], o.x, o.y);
                up2(acc2[e][j][1], o.z, o.w);
                *(float4*)(out + (size_t)es * Dc + dbase + 256 * j) = o;
            }
        }
    }
}

// ================= K2: vectorized reduce of xs partials + colstat finalize =========
__global__ void __launch_bounds__(256) k2_reduce_xs() {
    const int idx = blockIdx.x * 256 + threadIdx.x;    // 0..24575 float4 units
    const int b = idx / (ESc * Dc / 4);
    const int rem4 = idx % (ESc * Dc / 4);
    const int es = rem4 / (Dc / 4), d4 = rem4 % (Dc / 4);
    float4 s = make_float4(0.f, 0.f, 0.f, 0.f);
    const float4* base = (const float4*)(g_pxs) + (size_t)b * NCH1 * (ESc * Dc / 4) + rem4;
    #pragma unroll 8
    for (int c = 0; c < NCH1; ++c) {
        const float4 v = __ldg(base + (size_t)c * (ESc * Dc / 4));
        s.x += v.x; s.y += v.y; s.z += v.z; s.w += v.w;
    }
    const int e = es >> 1, sl = es & 1, row = b * 2 + sl;
    float* xs = (float*)g_xs2;
    const int d = d4 * 4;
    xs[((size_t)e * Dc + d + 0) * 16 + row] = s.x;
    xs[((size_t)e * Dc + d + 1) * 16 + row] = s.y;
    xs[((size_t)e * Dc + d + 2) * 16 + row] = s.z;
    xs[((size_t)e * Dc + d + 3) * 16 + row] = s.w;

    if (blockIdx.x == 0 && threadIdx.x < Bc * ESc) {
        const int i = threadIdx.x;
        const int bb = i >> 4, ees = i & 15;
        float M = -1e30f;
        #pragma unroll 8
        for (int c = 0; c < NCH1; ++c)
            M = fmaxf(M, g_mch[((size_t)bb * NCH1 + c) * ESc + ees]);
        float S = 0.f;
        #pragma unroll 8
        for (int c = 0; c < NCH1; ++c) {
            const size_t o = ((size_t)bb * NCH1 + c) * ESc + ees;
            S += __expf(g_mch[o] - M) * g_sch[o];
        }
        g_cmaxf[i] = M;
        g_inv[i] = 1.f / S;
    }
}

// ================= K5: FFN1 + GELU  (grid (48, 8), 256 thr) =================
#define K5_SMEM_BYTES (Dc * 8 * 8 + 2048 * 8)   // 65536
__global__ void __launch_bounds__(256, 3)
k5_ffn1(const float* __restrict__ w1, const float* __restrict__ b1) {
    extern __shared__ __align__(16) char k5smem[];
    u64* xsm = (u64*)k5smem;
    u64* red = xsm + Dc * 8;
    const int e = blockIdx.y;
    const int fbase = blockIdx.x * 64;
    const int tid = threadIdx.x;
    {
        const ulonglong2* src = (const ulonglong2*)(g_xs2 + (size_t)e * Dc * 8);
        ulonglong2* dst = (ulonglong2*)xsm;
        #pragma unroll
        for (int k = 0; k < 12; ++k) dst[tid + k * 256] = src[tid + k * 256];
    }
    __syncthreads();

    const int fi = tid & 15;
    const int rh = (tid >> 4) & 1;
    const int ds = tid >> 5;
    const int lid32 = tid & 31;
    const int f = fbase + fi * 4;

    u64 acc[4][4];
    #pragma unroll
    for (int j = 0; j < 4; ++j)
        #pragma unroll
        for (int r = 0; r < 4; ++r) acc[j][r] = 0ull;

    const float* w = w1 + (size_t)e * Dc * Hc + f;
    const ulonglong2* x2 = (const ulonglong2*)xsm;
    const int dlo = ds * 96;
    #pragma unroll 8
    for (int d = dlo; d < dlo + 96; ++d) {
        const float4 wv = __ldg((const float4*)(w + (size_t)d * Hc));
        const ulonglong2 xa = x2[d * 4 + rh * 2];
        const ulonglong2 xb = x2[d * 4 + rh * 2 + 1];
        const u64 w0 = dup2(wv.x), w1d = dup2(wv.y), w2 = dup2(wv.z), w3 = dup2(wv.w);
        fma2(acc[0][0], w0, xa.x); fma2(acc[0][1], w0, xa.y);
        fma2(acc[0][2], w0, xb.x); fma2(acc[0][3], w0, xb.y);
        fma2(acc[1][0], w1d, xa.x); fma2(acc[1][1], w1d, xa.y);
        fma2(acc[1][2], w1d, xb.x); fma2(acc[1][3], w1d, xb.y);
        fma2(acc[2][0], w2, xa.x); fma2(acc[2][1], w2, xa.y);
        fma2(acc[2][2], w2, xb.x); fma2(acc[2][3], w2, xb.y);
        fma2(acc[3][0], w3, xa.x); fma2(acc[3][1], w3, xa.y);
        fma2(acc[3][2], w3, xb.x); fma2(acc[3][3], w3, xb.y);
    }

    if (ds >= 4) {
        u64* r = red + ((ds - 4) * 32 + lid32) * 16;
        #pragma unroll
        for (int j = 0; j < 4; ++j)
            #pragma unroll
            for (int k = 0; k < 4; ++k) r[j * 4 + k] = acc[j][k];
    }
    __syncthreads();
    if (ds < 4) {
        const u64* r = red + (ds * 32 + lid32) * 16;
        #pragma unroll
        for (int j = 0; j < 4; ++j)
            #pragma unroll
            for (int k = 0; k < 4; ++k) acc[j][k] = add2(acc[j][k], r[j * 4 + k]);
    }
    __syncthreads();
    if (ds >= 2 && ds < 4) {
        u64* r = red + ((ds - 2) * 32 + lid32) * 16;
        #pragma unroll
        for (int j = 0; j < 4; ++j)
            #pragma unroll
            for (int k = 0; k < 4; ++k) r[j * 4 + k] = acc[j][k];
    }
    __syncthreads();
    if (ds < 2) {
        const u64* r = red + (ds * 32 + lid32) * 16;
        #pragma unroll
        for (int j = 0; j < 4; ++j)
            #pragma unroll
            for (int k = 0; k < 4; ++k) acc[j][k] = add2(acc[j][k], r[j * 4 + k]);
    }
    __syncthreads();
    if (ds == 1) {
        u64* r = red + lid32 * 16;
        #pragma unroll
        for (int j = 0; j < 4; ++j)
            #pragma unroll
            for (int k = 0; k < 4; ++k) r[j * 4 + k] = acc[j][k];
    }
    __syncthreads();
    if (ds == 0) {
        u64* r = red + lid32 * 16;
        #pragma unroll
        for (int j = 0; j < 4; ++j)
            #pragma unroll
            for (int k = 0; k < 4; ++k) r[j * 4 + k] = add2(acc[j][k], r[j * 4 + k]);
    }
    __syncthreads();
    #pragma unroll
    for (int q = 0; q < 2; ++q) {
        const int flat = tid * 2 + q;
        const int t32 = flat >> 4, j = flat & 15;
        const int fi2 = t32 & 15, rh2 = t32 >> 4;
        const int jf = j >> 2, jr = j & 3;
        const int f2 = fbase + fi2 * 4 + jf;
        const int rp = rh2 * 4 + jr;
        const float bv = __ldg(b1 + (size_t)e * Hc + f2);
        float lo, hi; up2(red[flat], lo, hi);
        g_h2[((size_t)e * Hc + f2) * 8 + rp] =
            pk2(gelu_exact(lo + bv), gelu_exact(hi + bv));
    }
}

// ================= K6: FFN2 + bias  (grid (48, 8), 256 thr) =================
__global__ void __launch_bounds__(256, 3)
k6_ffn2(const float* __restrict__ w2, const float* __restrict__ b2) {
    __shared__ __align__(16) u64 red[32 * 128];
    const int e = blockIdx.y;
    const int d0 = blockIdx.x * 16;
    const int tid = threadIdx.x;
    const int dq = tid & 3, rh = (tid >> 2) & 1, fs = tid >> 3;

    u64 acc[4][4];
    #pragma unroll
    for (int j = 0; j < 4; ++j)
        #pragma unroll
        for (int r = 0; r < 4; ++r) acc[j][r] = 0ull;

    const float* w = w2 + (size_t)e * Hc * Dc + d0 + dq * 4;
    const ulonglong2* h2 = (const ulonglong2*)(g_h2 + (size_t)e * Hc * 8);
    const int f0 = fs * 96;
    #pragma unroll 8
    for (int f = f0; f < f0 + 96; ++f) {
        const float4 wv = __ldg((const float4*)(w + (size_t)f * Dc));
        const ulonglong2 ha = h2[f * 4 + rh * 2];
        const ulonglong2 hb = h2[f * 4 + rh * 2 + 1];
        const u64 wd0 = dup2(wv.x), wd1 = dup2(wv.y), wd2 = dup2(wv.z), wd3 = dup2(wv.w);
        fma2(acc[0][0], wd0, ha.x); fma2(acc[0][1], wd0, ha.y);
        fma2(acc[0][2], wd0, hb.x); fma2(acc[0][3], wd0, hb.y);
        fma2(acc[1][0], wd1, ha.x); fma2(acc[1][1], wd1, ha.y);
        fma2(acc[1][2], wd1, hb.x); fma2(acc[1][3], wd1, hb.y);
        fma2(acc[2][0], wd2, ha.x); fma2(acc[2][1], wd2, ha.y);
        fma2(acc[2][2], wd2, hb.x); fma2(acc[2][3], wd2, hb.y);
        fma2(acc[3][0], wd3, ha.x); fma2(acc[3][1], wd3, ha.y);
        fma2(acc[3][2], wd3, hb.x); fma2(acc[3][3], wd3, hb.y);
    }
    #pragma unroll
    for (int j = 0; j < 4; ++j)
        #pragma unroll
        for (int r = 0; r < 4; ++r)
            red[fs * 128 + (dq * 4 + j) * 8 + rh * 4 + r] = acc[j][r];
    __syncthreads();
    if (tid < 128) {
        const int d_loc = tid >> 3, rp = tid & 7;
        u64 s = red[d_loc * 8 + rp];
        #pragma unroll 8
        for (int f2 = 1; f2 < 32; ++f2) s = add2(s, red[f2 * 128 + d_loc * 8 + rp]);
        float lo, hi; up2(s, lo, hi);
        const float bb2 = __ldg(b2 + (size_t)e * Dc + d0 + d_loc);
        const int r0 = 2 * rp, r1 = 2 * rp + 1;
        g_ys[((size_t)(r0 >> 1) * ESc + e * 2 + (r0 & 1)) * Dc + d0 + d_loc] = lo + bb2;
        g_ys[((size_t)(r1 >> 1) * ESc + e * 2 + (r1 & 1)) * Dc + d0 + d_loc] = hi + bb2;
    }
}

// ================= K7: combine softmax + y = c @ ys  (grid (64, 8)) =================
#define K7_SMEM_FLOATS (ESc * Dc + ESc * TOK7 + 32)
extern "C" __global__ void __launch_bounds__(256)
k7_combine(float* __restrict__ y) {
    extern __shared__ float smemf[];
    float* ysm = smemf;
    float* csm = smemf + ESc * Dc;
    float* cm  = smemf + ESc * Dc + ESc * TOK7;
    float* inv = cm + 16;

    const int b = blockIdx.y, chunk = blockIdx.x, tid = threadIdx.x;
    {
        const float4* src = (const float4*)(g_ys + (size_t)b * ESc * Dc);
        float4* dst = (float4*)ysm;
        #pragma unroll
        for (int k = 0; k < 12; ++k) dst[tid + k * 256] = src[tid + k * 256];
    }
    if (tid < 16) { cm[tid] = g_cmaxf[b * ESc + tid]; inv[tid] = g_inv[b * ESc + tid]; }
    __syncthreads();

    {
        const int i0 = tid * 4;
        const int es = i0 >> 6;
        const int t0 = i0 & 63;
        const float m = cm[es], iv = inv[es];
        const float* lp = g_logits + ((size_t)b * Nc + chunk * TOK7 + t0) * ESc + es;
        #pragma unroll
        for (int q = 0; q < 4; ++q)
            csm[es * TOK7 + t0 + q] = __expf(lp[q * ESc] - m) * iv;
    }
    __syncthreads();

    const int dg = tid & 63, tg = tid >> 6;
    const int dbase = dg * 4;
    float* yb = y + ((size_t)b * Nc + chunk * TOK7) * Dc;
    for (int tq = 0; tq < 4; ++tq) {
        const int trel = tg * 16 + tq * 4;
        u64 acc[4][3][2];
        #pragma unroll
        for (int t = 0; t < 4; ++t)
            #pragma unroll
            for (int j = 0; j < 3; ++j) { acc[t][j][0] = 0ull; acc[t][j][1] = 0ull; }
        #pragma unroll
        for (int es = 0; es < 16; ++es) {
            float4 c4 = *(const float4*)&csm[es * TOK7 + trel];
            u64 cd0 = dup2(c4.x), cd1 = dup2(c4.y), cd2 = dup2(c4.z), cd3 = dup2(c4.w);
            #pragma unroll
            for (int j = 0; j < 3; ++j) {
                float4 yv = *(const float4*)&ysm[es * Dc + dbase + 256 * j];
                u64 ylo = pk2(yv.x, yv.y), yhi = pk2(yv.z, yv.w);
                fma2(acc[0][j][0], cd0, ylo); fma2(acc[0][j][1], cd0, yhi);
                fma2(acc[1][j][0], cd1, ylo); fma2(acc[1][j][1], cd1, yhi);
                fma2(acc[2][j][0], cd2, ylo); fma2(acc[2][j][1], cd2, yhi);
                fma2(acc[3][j][0], cd3, ylo); fma2(acc[3][j][1], cd3, yhi);
            }
        }
        #pragma unroll
        for (int t = 0; t < 4; ++t) {
            float* yr = yb + (size_t)(trel + t) * Dc;
            #pragma unroll
            for (int j = 0; j < 3; ++j) {
                float4 o;
                up2(acc[t][j][0], o.x, o.y);
                up2(acc[t][j][1], o.z, o.w);
                *(float4*)(yr + dbase + 256 * j) = o;
            }
        }
    }
}

// ================= host =================
extern "C" void kernel_launch(void* const* d_in, const int* in_sizes, int n_in,
                              void* d_out, int out_size) {
    const float* x   = (const float*)d_in[0];
    const float* phi = (const float*)d_in[1];
    const float* w1  = (const float*)d_in[2];
    const float* b1  = (const float*)d_in[3];
    const float* w2  = (const float*)d_in[4];
    const float* b2  = (const float*)d_in[5];
    float* y = (float*)d_out;

    cudaFuncSetAttribute(k1_fused, cudaFuncAttributeMaxDynamicSharedMemorySize,
                         K1_SMEM_FLOATS * sizeof(float));
    cudaFuncSetAttribute(k5_ffn1, cudaFuncAttributeMaxDynamicSharedMemorySize,
                         K5_SMEM_BYTES);
    cudaFuncSetAttribute(k7_combine, cudaFuncAttributeMaxDynamicSharedMemorySize,
                         K7_SMEM_FLOATS * sizeof(float));
    (void)in_sizes; (void)n_in; (void)out_size;

    // 3 no-ops: 4th launch (profiled) = k1_fused
    kd_noop<<<1, 32>>>();
    kd_noop<<<1, 32>>>();
    kd_noop<<<1, 32>>>();
    k1_fused<<<dim3(NCH1, Bc), 256, K1_SMEM_FLOATS * sizeof(float)>>>(x, phi);
    k2_reduce_xs<<<96, 256>>>();
    k5_ffn1<<<dim3(Hc / 64, Ec), 256, K5_SMEM_BYTES>>>(w1, b1);
    k6_ffn2<<<dim3(Dc / 16, Ec), 256>>>(w2, b2);
    k7_combine<<<dim3(Nc / TOK7, Bc), 256, K7_SMEM_FLOATS * sizeof(float)>>>(y);
}

// round 17
// speedup vs baseline: 1.0793x; 1.0461x over previous
#include <cuda_runtime.h>
#include <math.h>

#define Bc 8
#define Nc 4096
#define Dc 768
#define Ec 8
#define ESc 16
#define Hc 3072
#define NCH1 64
#define TOK1 64
#define TOK7 64

typedef unsigned long long u64;
typedef unsigned int u32;

// ----------------- scratch -----------------
__device__ float g_logits[Bc * Nc * ESc];
__device__ float g_pxs[Bc * NCH1 * ESc * Dc];
__device__ __align__(16) u64 g_xs2[Ec * Dc * 8];       // [e][d][rp]
__device__ float g_mch[Bc * NCH1 * ESc];
__device__ float g_sch[Bc * NCH1 * ESc];
__device__ float g_cmaxf[Bc * ESc];
__device__ float g_inv[Bc * ESc];
__device__ __align__(16) u64 g_h2[Ec * Hc * 8];        // [e][f][rp]
__device__ float g_ys[Bc * ESc * Dc];

// ----------------- f32x2 helpers -----------------
__device__ __forceinline__ u64 pk2(float x, float y) {
    u64 r; asm("mov.b64 %0, {%1, %2};" : "=l"(r) : "f"(x), "f"(y)); return r;
}
__device__ __forceinline__ u64 dup2(float x) {
    u64 r; asm("mov.b64 %0, {%1, %1};" : "=l"(r) : "f"(x)); return r;
}
__device__ __forceinline__ void up2(u64 v, float& x, float& y) {
    asm("mov.b64 {%0, %1}, %2;" : "=f"(x), "=f"(y) : "l"(v));
}
__device__ __forceinline__ void fma2(u64& d, u64 a, u64 b) {
    asm("fma.rn.f32x2 %0, %1, %2, %0;" : "+l"(d) : "l"(a), "l"(b));
}
__device__ __forceinline__ u64 add2(u64 a, u64 b) {
    u64 r; asm("add.rn.f32x2 %0, %1, %2;" : "=l"(r) : "l"(a), "l"(b)); return r;
}
__device__ __forceinline__ float gelu_exact(float v) {
    return 0.5f * v * (1.0f + erff(v * 0.70710678118654752f));
}

// ---- k1 smem float offsets (red ALIASED onto xT) ----
#define OFF_PHI  0                      // 12288 floats (u64[768*8])
#define OFF_XT   12288                  // 64 x 65 = 4160 floats (mainloop only)
#define OFF_RED  12288                  // aliased: 2080 u64 capacity (post-mainloop)
#define OFF_LSM  16448                  // 64 x 16
#define OFF_DSM  17472                  // 64 x 16
#define OFF_GM   18496                  // 16 x 16
#define OFF_PS   18752                  // 16 x 16
#define OFF_CM   19008                  // 16
#define K1_SMEM_FLOATS 19024            // 76096 B

// ================= K1: fused logits + dispatch softmax + chunk colstats + partial xs ===
// grid (64, 8), 256 thr
extern "C" __global__ void __launch_bounds__(256)
k1_fused(const float* __restrict__ x, const float* __restrict__ phi) {
    extern __shared__ float smemf[];
    u64*   phiD = (u64*)(smemf + OFF_PHI);
    float* xT   = smemf + OFF_XT;
    u64*   red  = (u64*)(smemf + OFF_RED);   // aliases xT — only used after mainloop
    float* lsm  = smemf + OFF_LSM;
    float* dsm  = smemf + OFF_DSM;
    float* gm   = smemf + OFF_GM;
    float* ps   = smemf + OFF_PS;
    float* cm   = smemf + OFF_CM;

    const int b = blockIdx.y, chunk = blockIdx.x;
    const int tid = threadIdx.x;
    const int lane = tid & 31, wid = tid >> 5;
    const float* xc = x + ((size_t)b * Nc + chunk * TOK1) * Dc;

    {   // phi [768][16] -> u64 pairs, straight copy
        const u64* ph = (const u64*)phi;
        for (int i = tid; i < Dc * 8; i += 256) phiD[i] = ph[i];
    }

    // ---- Phase A: logits. warp = K-segment (8 d per 64-d block); lane owns 2 tokens ---
    u64 acc[16];               // [0..7]: token=lane, [8..15]: token=lane+32
    #pragma unroll
    for (int j = 0; j < 16; ++j) acc[j] = 0ull;

    for (int db = 0; db < 12; ++db) {
        const int d0 = db * 64;
        __syncthreads();
        // stage x[64 tok][64 d] transposed via float4 loads
        #pragma unroll
        for (int k = 0; k < 4; ++k) {
            const int idx = tid + k * 256;          // 0..1023
            const int t = idx >> 4, dd4 = idx & 15;
            const float4 v = __ldg((const float4*)(xc + (size_t)t * Dc + d0 + dd4 * 4));
            xT[(dd4 * 4 + 0) * 65 + t] = v.x;
            xT[(dd4 * 4 + 1) * 65 + t] = v.y;
            xT[(dd4 * 4 + 2) * 65 + t] = v.z;
            xT[(dd4 * 4 + 3) * 65 + t] = v.w;
        }
        __syncthreads();
        const ulonglong2* pp = (const ulonglong2*)phiD;
        #pragma unroll
        for (int i = 0; i < 8; ++i) {
            const int dd = wid * 8 + i;
            const int d = d0 + dd;
            const u64 xa = dup2(xT[dd * 65 + lane]);
            const u64 xb = dup2(xT[dd * 65 + 32 + lane]);
            ulonglong2 q0 = pp[d * 4 + 0];
            ulonglong2 q1 = pp[d * 4 + 1];
            ulonglong2 q2 = pp[d * 4 + 2];
            ulonglong2 q3 = pp[d * 4 + 3];
            fma2(acc[0], xa, q0.x); fma2(acc[1], xa, q0.y);
            fma2(acc[2], xa, q1.x); fma2(acc[3], xa, q1.y);
            fma2(acc[4], xa, q2.x); fma2(acc[5], xa, q2.y);
            fma2(acc[6], xa, q3.x); fma2(acc[7], xa, q3.y);
            fma2(acc[8],  xb, q0.x); fma2(acc[9],  xb, q0.y);
            fma2(acc[10], xb, q1.x); fma2(acc[11], xb, q1.y);
            fma2(acc[12], xb, q2.x); fma2(acc[13], xb, q2.y);
            fma2(acc[14], xb, q3.x); fma2(acc[15], xb, q3.y);
        }
    }
    __syncthreads();      // xT dead; red (aliased) becomes live

    // ---- 3-stage tree reduce over 8 warps ----
    if (wid >= 4) {
        u64* r = red + ((wid - 4) * 32 + lane) * 16;
        #pragma unroll
        for (int j = 0; j < 16; ++j) r[j] = acc[j];
    }
    __syncthreads();
    if (wid < 4) {
        const u64* r = red + (wid * 32 + lane) * 16;
        #pragma unroll
        for (int j = 0; j < 16; ++j) acc[j] = add2(acc[j], r[j]);
    }
    __syncthreads();
    if (wid >= 2 && wid < 4) {
        u64* r = red + ((wid - 2) * 32 + lane) * 16;
        #pragma unroll
        for (int j = 0; j < 16; ++j) r[j] = acc[j];
    }
    __syncthreads();
    if (wid < 2) {
        const u64* r = red + (wid * 32 + lane) * 16;
        #pragma unroll
        for (int j = 0; j < 16; ++j) acc[j] = add2(acc[j], r[j]);
    }
    __syncthreads();
    if (wid == 1) {
        u64* r = red + lane * 16;
        #pragma unroll
        for (int j = 0; j < 16; ++j) r[j] = acc[j];
    }
    __syncthreads();
    if (wid == 0) {
        const u64* r = red + lane * 16;
        #pragma unroll
        for (int j = 0; j < 16; ++j) acc[j] = add2(acc[j], r[j]);
        u64* dl = (u64*)dsm;
        u64* ll = (u64*)lsm;
        #pragma unroll
        for (int h = 0; h < 2; ++h) {
            float l[16];
            #pragma unroll
            for (int j = 0; j < 8; ++j) up2(acc[h * 8 + j], l[2 * j], l[2 * j + 1]);
            float m = l[0];
            #pragma unroll
            for (int es = 1; es < 16; ++es) m = fmaxf(m, l[es]);
            float s = 0.f;
            float p[16];
            #pragma unroll
            for (int es = 0; es < 16; ++es) { p[es] = __expf(l[es] - m); s += p[es]; }
            const float inv = 1.f / s;
            const int tk = lane + h * 32;
            #pragma unroll
            for (int j = 0; j < 8; ++j) {
                dl[tk * 8 + j] = pk2(p[2 * j] * inv, p[2 * j + 1] * inv);
                ll[tk * 8 + j] = pk2(l[2 * j], l[2 * j + 1]);
            }
        }
    }
    __syncthreads();

    {   // raw logits -> global
        const size_t lbase = ((size_t)b * Nc + chunk * TOK1) * ESc;
        #pragma unroll
        for (int k = 0; k < 4; ++k) g_logits[lbase + tid + k * 256] = lsm[tid + k * 256];
    }

    // ---- Phase B: per-chunk column stats (16 groups x 4 tokens) ----
    {
        const int g = tid >> 4, es = tid & 15;
        float m = -1e30f;
        #pragma unroll
        for (int t4 = 0; t4 < 4; ++t4) m = fmaxf(m, lsm[(g * 4 + t4) * ESc + es]);
        gm[g * 16 + es] = m;
    }
    __syncthreads();
    if (tid < 16) {
        float m = gm[tid];
        #pragma unroll
        for (int g = 1; g < 16; ++g) m = fmaxf(m, gm[g * 16 + tid]);
        cm[tid] = m;
    }
    __syncthreads();
    {
        const int g = tid >> 4, es = tid & 15;
        const float m = cm[es];
        float p = 0.f;
        #pragma unroll
        for (int t4 = 0; t4 < 4; ++t4) p += __expf(lsm[(g * 4 + t4) * ESc + es] - m);
        ps[g * 16 + es] = p;
    }
    __syncthreads();
    if (tid < 16) {
        float s = 0.f;
        #pragma unroll
        for (int g = 0; g < 16; ++g) s += ps[g * 16 + tid];
        g_mch[((size_t)b * NCH1 + chunk) * ESc + tid] = cm[tid];
        g_sch[((size_t)b * NCH1 + chunk) * ESc + tid] = s;
    }

    // ---- Phase C: partial xs, thread = (12 d as 3 float4) x (4 es), unroll 4 ----
    {
        const int f4i = tid & 63;
        const int esq = tid >> 6;
        u64 acc2[4][3][2];
        #pragma unroll
        for (int e = 0; e < 4; ++e)
            #pragma unroll
            for (int j = 0; j < 3; ++j) { acc2[e][j][0] = 0ull; acc2[e][j][1] = 0ull; }

        const int dbase = f4i * 4;
        #pragma unroll 4
        for (int t = 0; t < TOK1; ++t) {
            const float4 xv0 = __ldg((const float4*)(xc + (size_t)t * Dc + dbase));
            const float4 xv1 = __ldg((const float4*)(xc + (size_t)t * Dc + dbase + 256));
            const float4 xv2 = __ldg((const float4*)(xc + (size_t)t * Dc + dbase + 512));
            const u64 x0l = pk2(xv0.x, xv0.y), x0h = pk2(xv0.z, xv0.w);
            const u64 x1l = pk2(xv1.x, xv1.y), x1h = pk2(xv1.z, xv1.w);
            const u64 x2l = pk2(xv2.x, xv2.y), x2h = pk2(xv2.z, xv2.w);
            const float4 dv = *(const float4*)&dsm[t * ESc + esq * 4];
            const u64 w0 = dup2(dv.x), w1 = dup2(dv.y), w2 = dup2(dv.z), w3 = dup2(dv.w);
            fma2(acc2[0][0][0], w0, x0l); fma2(acc2[0][0][1], w0, x0h);
            fma2(acc2[0][1][0], w0, x1l); fma2(acc2[0][1][1], w0, x1h);
            fma2(acc2[0][2][0], w0, x2l); fma2(acc2[0][2][1], w0, x2h);
            fma2(acc2[1][0][0], w1, x0l); fma2(acc2[1][0][1], w1, x0h);
            fma2(acc2[1][1][0], w1, x1l); fma2(acc2[1][1][1], w1, x1h);
            fma2(acc2[1][2][0], w1, x2l); fma2(acc2[1][2][1], w1, x2h);
            fma2(acc2[2][0][0], w2, x0l); fma2(acc2[2][0][1], w2, x0h);
            fma2(acc2[2][1][0], w2, x1l); fma2(acc2[2][1][1], w2, x1h);
            fma2(acc2[2][2][0], w2, x2l); fma2(acc2[2][2][1], w2, x2h);
            fma2(acc2[3][0][0], w3, x0l); fma2(acc2[3][0][1], w3, x0h);
            fma2(acc2[3][1][0], w3, x1l); fma2(acc2[3][1][1], w3, x1h);
            fma2(acc2[3][2][0], w3, x2l); fma2(acc2[3][2][1], w3, x2h);
        }
        float* out = g_pxs + ((size_t)(b * NCH1 + chunk) * ESc) * Dc;
        #pragma unroll
        for (int e = 0; e < 4; ++e) {
            const int es = esq * 4 + e;
            #pragma unroll
            for (int j = 0; j < 3; ++j) {
                float4 o;
                up2(acc2[e][j][0], o.x, o.y);
                up2(acc2[e][j][1], o.z, o.w);
                *(float4*)(out + (size_t)es * Dc + dbase + 256 * j) = o;
            }
        }
    }
}

// ================= K2: vectorized reduce of xs partials + colstat finalize =========
__global__ void __launch_bounds__(256) k2_reduce_xs() {
    const int idx = blockIdx.x * 256 + threadIdx.x;    // 0..24575 float4 units
    const int b = idx / (ESc * Dc / 4);
    const int rem4 = idx % (ESc * Dc / 4);
    const int es = rem4 / (Dc / 4), d4 = rem4 % (Dc / 4);
    float4 s = make_float4(0.f, 0.f, 0.f, 0.f);
    const float4* base = (const float4*)(g_pxs) + (size_t)b * NCH1 * (ESc * Dc / 4) + rem4;
    #pragma unroll 8
    for (int c = 0; c < NCH1; ++c) {
        const float4 v = __ldg(base + (size_t)c * (ESc * Dc / 4));
        s.x += v.x; s.y += v.y; s.z += v.z; s.w += v.w;
    }
    const int e = es >> 1, sl = es & 1, row = b * 2 + sl;
    float* xs = (float*)g_xs2;
    const int d = d4 * 4;
    xs[((size_t)e * Dc + d + 0) * 16 + row] = s.x;
    xs[((size_t)e * Dc + d + 1) * 16 + row] = s.y;
    xs[((size_t)e * Dc + d + 2) * 16 + row] = s.z;
    xs[((size_t)e * Dc + d + 3) * 16 + row] = s.w;

    if (blockIdx.x == 0 && threadIdx.x < Bc * ESc) {
        const int i = threadIdx.x;
        const int bb = i >> 4, ees = i & 15;
        float M = -1e30f;
        #pragma unroll 8
        for (int c = 0; c < NCH1; ++c)
            M = fmaxf(M, g_mch[((size_t)bb * NCH1 + c) * ESc + ees]);
        float S = 0.f;
        #pragma unroll 8
        for (int c = 0; c < NCH1; ++c) {
            const size_t o = ((size_t)bb * NCH1 + c) * ESc + ees;
            S += __expf(g_mch[o] - M) * g_sch[o];
        }
        g_cmaxf[i] = M;
        g_inv[i] = 1.f / S;
    }
}

// ================= K5: FFN1 + GELU  (grid (48, 8), 256 thr) =================
#define K5_SMEM_BYTES (Dc * 8 * 8 + 2048 * 8)   // 65536
__global__ void __launch_bounds__(256, 3)
k5_ffn1(const float* __restrict__ w1, const float* __restrict__ b1) {
    extern __shared__ __align__(16) char k5smem[];
    u64* xsm = (u64*)k5smem;
    u64* red = xsm + Dc * 8;
    const int e = blockIdx.y;
    const int fbase = blockIdx.x * 64;
    const int tid = threadIdx.x;
    {
        const ulonglong2* src = (const ulonglong2*)(g_xs2 + (size_t)e * Dc * 8);
        ulonglong2* dst = (ulonglong2*)xsm;
        #pragma unroll
        for (int k = 0; k < 12; ++k) dst[tid + k * 256] = src[tid + k * 256];
    }
    __syncthreads();

    const int fi = tid & 15;
    const int rh = (tid >> 4) & 1;
    const int ds = tid >> 5;
    const int lid32 = tid & 31;
    const int f = fbase + fi * 4;

    u64 acc[4][4];
    #pragma unroll
    for (int j = 0; j < 4; ++j)
        #pragma unroll
        for (int r = 0; r < 4; ++r) acc[j][r] = 0ull;

    const float* w = w1 + (size_t)e * Dc * Hc + f;
    const ulonglong2* x2 = (const ulonglong2*)xsm;
    const int dlo = ds * 96;
    #pragma unroll 8
    for (int d = dlo; d < dlo + 96; ++d) {
        const float4 wv = __ldg((const float4*)(w + (size_t)d * Hc));
        const ulonglong2 xa = x2[d * 4 + rh * 2];
        const ulonglong2 xb = x2[d * 4 + rh * 2 + 1];
        const u64 w0 = dup2(wv.x), w1d = dup2(wv.y), w2 = dup2(wv.z), w3 = dup2(wv.w);
        fma2(acc[0][0], w0, xa.x); fma2(acc[0][1], w0, xa.y);
        fma2(acc[0][2], w0, xb.x); fma2(acc[0][3], w0, xb.y);
        fma2(acc[1][0], w1d, xa.x); fma2(acc[1][1], w1d, xa.y);
        fma2(acc[1][2], w1d, xb.x); fma2(acc[1][3], w1d, xb.y);
        fma2(acc[2][0], w2, xa.x); fma2(acc[2][1], w2, xa.y);
        fma2(acc[2][2], w2, xb.x); fma2(acc[2][3], w2, xb.y);
        fma2(acc[3][0], w3, xa.x); fma2(acc[3][1], w3, xa.y);
        fma2(acc[3][2], w3, xb.x); fma2(acc[3][3], w3, xb.y);
    }

    if (ds >= 4) {
        u64* r = red + ((ds - 4) * 32 + lid32) * 16;
        #pragma unroll
        for (int j = 0; j < 4; ++j)
            #pragma unroll
            for (int k = 0; k < 4; ++k) r[j * 4 + k] = acc[j][k];
    }
    __syncthreads();
    if (ds < 4) {
        const u64* r = red + (ds * 32 + lid32) * 16;
        #pragma unroll
        for (int j = 0; j < 4; ++j)
            #pragma unroll
            for (int k = 0; k < 4; ++k) acc[j][k] = add2(acc[j][k], r[j * 4 + k]);
    }
    __syncthreads();
    if (ds >= 2 && ds < 4) {
        u64* r = red + ((ds - 2) * 32 + lid32) * 16;
        #pragma unroll
        for (int j = 0; j < 4; ++j)
            #pragma unroll
            for (int k = 0; k < 4; ++k) r[j * 4 + k] = acc[j][k];
    }
    __syncthreads();
    if (ds < 2) {
        const u64* r = red + (ds * 32 + lid32) * 16;
        #pragma unroll
        for (int j = 0; j < 4; ++j)
            #pragma unroll
            for (int k = 0; k < 4; ++k) acc[j][k] = add2(acc[j][k], r[j * 4 + k]);
    }
    __syncthreads();
    if (ds == 1) {
        u64* r = red + lid32 * 16;
        #pragma unroll
        for (int j = 0; j < 4; ++j)
            #pragma unroll
            for (int k = 0; k < 4; ++k) r[j * 4 + k] = acc[j][k];
    }
    __syncthreads();
    if (ds == 0) {
        u64* r = red + lid32 * 16;
        #pragma unroll
        for (int j = 0; j < 4; ++j)
            #pragma unroll
            for (int k = 0; k < 4; ++k) r[j * 4 + k] = add2(acc[j][k], r[j * 4 + k]);
    }
    __syncthreads();
    #pragma unroll
    for (int q = 0; q < 2; ++q) {
        const int flat = tid * 2 + q;
        const int t32 = flat >> 4, j = flat & 15;
        const int fi2 = t32 & 15, rh2 = t32 >> 4;
        const int jf = j >> 2, jr = j & 3;
        const int f2 = fbase + fi2 * 4 + jf;
        const int rp = rh2 * 4 + jr;
        const float bv = __ldg(b1 + (size_t)e * Hc + f2);
        float lo, hi; up2(red[flat], lo, hi);
        g_h2[((size_t)e * Hc + f2) * 8 + rp] =
            pk2(gelu_exact(lo + bv), gelu_exact(hi + bv));
    }
}

// ================= K6: FFN2 + bias  (grid (48, 8), 256 thr) =================
__global__ void __launch_bounds__(256, 3)
k6_ffn2(const float* __restrict__ w2, const float* __restrict__ b2) {
    __shared__ __align__(16) u64 red[32 * 128];
    const int e = blockIdx.y;
    const int d0 = blockIdx.x * 16;
    const int tid = threadIdx.x;
    const int dq = tid & 3, rh = (tid >> 2) & 1, fs = tid >> 3;

    u64 acc[4][4];
    #pragma unroll
    for (int j = 0; j < 4; ++j)
        #pragma unroll
        for (int r = 0; r < 4; ++r) acc[j][r] = 0ull;

    const float* w = w2 + (size_t)e * Hc * Dc + d0 + dq * 4;
    const ulonglong2* h2 = (const ulonglong2*)(g_h2 + (size_t)e * Hc * 8);
    const int f0 = fs * 96;
    #pragma unroll 8
    for (int f = f0; f < f0 + 96; ++f) {
        const float4 wv = __ldg((const float4*)(w + (size_t)f * Dc));
        const ulonglong2 ha = h2[f * 4 + rh * 2];
        const ulonglong2 hb = h2[f * 4 + rh * 2 + 1];
        const u64 wd0 = dup2(wv.x), wd1 = dup2(wv.y), wd2 = dup2(wv.z), wd3 = dup2(wv.w);
        fma2(acc[0][0], wd0, ha.x); fma2(acc[0][1], wd0, ha.y);
        fma2(acc[0][2], wd0, hb.x); fma2(acc[0][3], wd0, hb.y);
        fma2(acc[1][0], wd1, ha.x); fma2(acc[1][1], wd1, ha.y);
        fma2(acc[1][2], wd1, hb.x); fma2(acc[1][3], wd1, hb.y);
        fma2(acc[2][0], wd2, ha.x); fma2(acc[2][1], wd2, ha.y);
        fma2(acc[2][2], wd2, hb.x); fma2(acc[2][3], wd2, hb.y);
        fma2(acc[3][0], wd3, ha.x); fma2(acc[3][1], wd3, ha.y);
        fma2(acc[3][2], wd3, hb.x); fma2(acc[3][3], wd3, hb.y);
    }
    #pragma unroll
    for (int j = 0; j < 4; ++j)
        #pragma unroll
        for (int r = 0; r < 4; ++r)
            red[fs * 128 + (dq * 4 + j) * 8 + rh * 4 + r] = acc[j][r];
    __syncthreads();
    if (tid < 128) {
        const int d_loc = tid >> 3, rp = tid & 7;
        u64 s = red[d_loc * 8 + rp];
        #pragma unroll 8
        for (int f2 = 1; f2 < 32; ++f2) s = add2(s, red[f2 * 128 + d_loc * 8 + rp]);
        float lo, hi; up2(s, lo, hi);
        const float bb2 = __ldg(b2 + (size_t)e * Dc + d0 + d_loc);
        const int r0 = 2 * rp, r1 = 2 * rp + 1;
        g_ys[((size_t)(r0 >> 1) * ESc + e * 2 + (r0 & 1)) * Dc + d0 + d_loc] = lo + bb2;
        g_ys[((size_t)(r1 >> 1) * ESc + e * 2 + (r1 & 1)) * Dc + d0 + d_loc] = hi + bb2;
    }
}

// ================= K7: combine softmax + y = c @ ys  (grid (64, 8, 2)) =================
// z = d-half: each block covers d in [z*384, z*384+384)
#define K7_SMEM_FLOATS (ESc * 384 + ESc * TOK7 + 32)   // 6144+1024+32 = 7200 (28.8KB)
extern "C" __global__ void __launch_bounds__(256)
k7_combine(float* __restrict__ y) {
    extern __shared__ float smemf[];
    float* ysm = smemf;                       // [16][384]
    float* csm = smemf + ESc * 384;           // [16][64]
    float* cm  = smemf + ESc * 384 + ESc * TOK7;
    float* inv = cm + 16;

    const int b = blockIdx.y, chunk = blockIdx.x, z = blockIdx.z;
    const int tid = threadIdx.x;
    {   // stage half of ys: 6144 floats = 1536 float4
        const float4* src = (const float4*)(g_ys + (size_t)b * ESc * Dc);
        float4* dst = (float4*)ysm;
        #pragma unroll
        for (int k = 0; k < 6; ++k) {
            const int i = tid + k * 256;            // 0..1535
            const int es = i / 96, dl4 = i % 96;
            dst[es * 96 + dl4] = src[es * 192 + z * 96 + dl4];
        }
    }
    if (tid < 16) { cm[tid] = g_cmaxf[b * ESc + tid]; inv[tid] = g_inv[b * ESc + tid]; }
    __syncthreads();

    {   // combine weights: 1024 entries, 4 per thread
        const int i0 = tid * 4;
        const int es = i0 >> 6;
        const int t0 = i0 & 63;
        const float m = cm[es], iv = inv[es];
        const float* lp = g_logits + ((size_t)b * Nc + chunk * TOK7 + t0) * ESc + es;
        #pragma unroll
        for (int q = 0; q < 4; ++q)
            csm[es * TOK7 + t0 + q] = __expf(lp[q * ESc] - m) * iv;
    }
    __syncthreads();

    const int dg = tid & 31, tg = tid >> 5;       // 32 d-groups, 8 token-groups
    const int dbase = dg * 4;                     // + 128*j, j<3 -> covers 384
    float* yb = y + ((size_t)b * Nc + chunk * TOK7) * Dc + z * 384;
    for (int tq = 0; tq < 2; ++tq) {
        const int trel = tg * 8 + tq * 4;
        u64 acc[4][3][2];
        #pragma unroll
        for (int t = 0; t < 4; ++t)
            #pragma unroll
            for (int j = 0; j < 3; ++j) { acc[t][j][0] = 0ull; acc[t][j][1] = 0ull; }
        #pragma unroll
        for (int es = 0; es < 16; ++es) {
            float4 c4 = *(const float4*)&csm[es * TOK7 + trel];
            u64 cd0 = dup2(c4.x), cd1 = dup2(c4.y), cd2 = dup2(c4.z), cd3 = dup2(c4.w);
            #pragma unroll
            for (int j = 0; j < 3; ++j) {
                float4 yv = *(const float4*)&ysm[es * 384 + dbase + 128 * j];
                u64 ylo = pk2(yv.x, yv.y), yhi = pk2(yv.z, yv.w);
                fma2(acc[0][j][0], cd0, ylo); fma2(acc[0][j][1], cd0, yhi);
                fma2(acc[1][j][0], cd1, ylo); fma2(acc[1][j][1], cd1, yhi);
                fma2(acc[2][j][0], cd2, ylo); fma2(acc[2][j][1], cd2, yhi);
                fma2(acc[3][j][0], cd3, ylo); fma2(acc[3][j][1], cd3, yhi);
            }
        }
        #pragma unroll
        for (int t = 0; t < 4; ++t) {
            float* yr = yb + (size_t)(trel + t) * Dc;
            #pragma unroll
            for (int j = 0; j < 3; ++j) {
                float4 o;
                up2(acc[t][j][0], o.x, o.y);
                up2(acc[t][j][1], o.z, o.w);
                *(float4*)(yr + dbase + 128 * j) = o;
            }
        }
    }
}

// ================= host =================
extern "C" void kernel_launch(void* const* d_in, const int* in_sizes, int n_in,
                              void* d_out, int out_size) {
    const float* x   = (const float*)d_in[0];
    const float* phi = (const float*)d_in[1];
    const float* w1  = (const float*)d_in[2];
    const float* b1  = (const float*)d_in[3];
    const float* w2  = (const float*)d_in[4];
    const float* b2  = (const float*)d_in[5];
    float* y = (float*)d_out;

    cudaFuncSetAttribute(k1_fused, cudaFuncAttributeMaxDynamicSharedMemorySize,
                         K1_SMEM_FLOATS * sizeof(float));
    cudaFuncSetAttribute(k5_ffn1, cudaFuncAttributeMaxDynamicSharedMemorySize,
                         K5_SMEM_BYTES);
    cudaFuncSetAttribute(k7_combine, cudaFuncAttributeMaxDynamicSharedMemorySize,
                         K7_SMEM_FLOATS * sizeof(float));
    (void)in_sizes; (void)n_in; (void)out_size;

    k1_fused<<<dim3(NCH1, Bc), 256, K1_SMEM_FLOATS * sizeof(float)>>>(x, phi);
    k2_reduce_xs<<<96, 256>>>();
    k5_ffn1<<<dim3(Hc / 64, Ec), 256, K5_SMEM_BYTES>>>(w1, b1);
    k6_ffn2<<<dim3(Dc / 16, Ec), 256>>>(w2, b2);
    k7_combine<<<dim3(Nc / TOK7, Bc, 2), 256, K7_SMEM_FLOATS * sizeof(float)>>>(y);
}